// round 14
// baseline (speedup 1.0000x reference)
#include <cuda_runtime.h>
#include <cuda.h>
#include <cuda_fp16.h>
#include <cstdint>

// ---------------- problem constants ----------------
static constexpr int BATCH = 8192;
static constexpr int IDIM  = 1024;
static constexpr int ODIM  = 1024;
static constexpr int NDEG  = 9;                 // DEGREE+1
static constexpr int KTOT  = NDEG * IDIM;       // 9216, k = d*1024 + i

static constexpr float A_SCALE   = 16.0f;
static constexpr float B_SCALE   = 4096.0f;
static constexpr float OUT_SCALE = 1.0f / (16.0f * 4096.0f);

// ---------------- GEMM config (persistent, k-unit balanced) ----------------
static constexpr int BM = 128, BN = 128;
static constexpr int KPT = KTOT / 128;               // 72 k-iters (128-wide) per mn tile
static constexpr int MNTILES = (ODIM / BN) * (BATCH / BM);  // 512
static constexpr int NU = MNTILES * KPT;             // 36864 total k-units
static constexpr int STAGES = 3;
static constexpr int SUB_TILE   = BM * 128;          // 16384 bytes (one 64-chunk)
static constexpr int STAGE_BYTES = 4 * SUB_TILE;     // A0 A1 B0 B1 = 65536
static constexpr int SMEM_BYTES  = 2048 + STAGES * STAGE_BYTES; // 198656

// ---------------- scratch (static device globals; no cudaMalloc allowed) ----
__device__ __half g_A[(size_t)BATCH * KTOT];   // ~151 MB
__device__ __half g_B[(size_t)ODIM  * KTOT];   // ~19 MB

// ---------------- PTX helpers ----------------
__device__ __forceinline__ uint32_t smem_u32(const void* p) {
    uint32_t a;
    asm("{ .reg .u64 t; cvta.to.shared.u64 t, %1; cvt.u32.u64 %0, t; }" : "=r"(a) : "l"(p));
    return a;
}
__device__ __forceinline__ uint32_t elect_one() {
    uint32_t pred;
    asm volatile("{\n\t.reg .pred p;\n\telect.sync _|p, 0xFFFFFFFF;\n\tselp.b32 %0, 1, 0, p;\n\t}"
                 : "=r"(pred));
    return pred;
}

#define MBAR_INIT(addr, cnt) \
    asm volatile("mbarrier.init.shared.b64 [%0], %1;" :: "r"(addr), "r"(cnt) : "memory")
#define FENCE_PROXY_ASYNC() \
    asm volatile("fence.proxy.async.shared::cta;" ::: "memory")
#define MBAR_EXPECT_TX(addr, bytes) \
    asm volatile("mbarrier.arrive.expect_tx.shared.b64 _, [%0], %1;" :: "r"(addr), "r"(bytes) : "memory")
#define MBAR_ARRIVE(addr) \
    asm volatile("mbarrier.arrive.shared.b64 _, [%0];" :: "r"(addr) : "memory")

#define MBAR_WAIT(addr, parity) do {                                              \
    uint32_t _m = (addr); uint32_t _p = (parity); uint32_t _done;                 \
    asm volatile("{\n\t.reg .pred p;\n\t"                                         \
        "mbarrier.try_wait.parity.acquire.cta.shared::cta.b64 p, [%1], %2;\n\t"   \
        "selp.b32 %0, 1, 0, p;\n\t}"                                              \
        : "=r"(_done) : "r"(_m), "r"(_p) : "memory");                             \
    if (!_done) {                                                                 \
        asm volatile("{\n\t.reg .pred P1;\n\t"                                    \
            "WAIT_LOOP_%=:\n\t"                                                   \
            "mbarrier.try_wait.parity.acquire.cta.shared::cta.b64 P1, [%0], %1, 0x989680;\n\t" \
            "@P1 bra.uni WAIT_DONE_%=;\n\t"                                       \
            "bra.uni WAIT_LOOP_%=;\n\t"                                           \
            "WAIT_DONE_%=:\n\t}"                                                  \
            :: "r"(_m), "r"(_p) : "memory");                                      \
    }                                                                             \
} while (0)

#define TMA_LOAD_2D(smem_addr, tmap_ptr, cx, cy, mbar)                                     \
    asm volatile("cp.async.bulk.tensor.2d.shared::cta.global.tile.mbarrier::complete_tx::bytes " \
                 "[%0], [%1, {%2, %3}], [%4];"                                             \
                 :: "r"(smem_addr), "l"(tmap_ptr), "r"(cx), "r"(cy), "r"(mbar) : "memory")

#define LDSM_X4(r0, r1, r2, r3, addr)                                          \
    asm volatile("ldmatrix.sync.aligned.m8n8.x4.shared.b16 {%0,%1,%2,%3}, [%4];" \
                 : "=r"(r0), "=r"(r1), "=r"(r2), "=r"(r3) : "r"(addr))

#define MMA_16816(c, a0, a1, a2, a3, b0, b1)                                   \
    asm volatile("mma.sync.aligned.m16n8k16.row.col.f32.f16.f16.f32 "          \
                 "{%0,%1,%2,%3}, {%4,%5,%6,%7}, {%8,%9}, {%0,%1,%2,%3};"       \
                 : "+f"((c)[0]), "+f"((c)[1]), "+f"((c)[2]), "+f"((c)[3])      \
                 : "r"(a0), "r"(a1), "r"(a2), "r"(a3), "r"(b0), "r"(b1))

#define RED_ADD_V2F32(addr, vx, vy)                                            \
    asm volatile("red.global.add.v2.f32 [%0], {%1, %2};"                       \
                 :: "l"(addr), "f"(vx), "f"(vy) : "memory")

// ---------------- kernel 0: zero output ------------------------------------
__global__ void __launch_bounds__(256) zero_kernel(float* __restrict__ out) {
    size_t idx = ((size_t)blockIdx.x * 256 + threadIdx.x) * 4;
    *reinterpret_cast<float4*>(out + idx) = make_float4(0.f, 0.f, 0.f, 0.f);
}

// ---------------- kernel 1: Hermite basis -> fp16 A [BATCH, KTOT] ----------
__device__ __forceinline__ void hermite_eval(float xin, float* h) {
    const float e2x = __expf(2.0f * xin);
    const float th = 1.0f - __fdividef(2.0f, e2x + 1.0f);   // tanh(xin)
    const float t = th * 5.123105625617661f;                 // sqrt(17)+1
    const float g = __expf(-0.5f * t * t);
    h[0] = 0.7511255444649425f * g;                    // pi^-1/4 * gauss
    h[1] = 1.0622519320271968f * t * g;                // sqrt2 * pi^-1/4 * t * gauss
    const float ca[9] = {0.f, 0.f, 1.0f, 0.816496580927726f, 0.7071067811865476f,
                         0.6324555320336759f, 0.5773502691896258f,
                         0.5345224838248488f, 0.5f};
    const float cb[9] = {0.f, 0.f, 0.7071067811865476f, 0.816496580927726f,
                         0.8660254037844386f, 0.8944271909999159f,
                         0.9128709291752769f, 0.9258200997725514f, 0.9354143466934853f};
#pragma unroll
    for (int d = 2; d < 9; d++) h[d] = ca[d] * t * h[d - 1] - cb[d] * h[d - 2];
}

__global__ void __launch_bounds__(256) hermite_basis_kernel(const float* __restrict__ x,
                                                            __half* __restrict__ A) {
    unsigned idx = blockIdx.x * 256u + threadIdx.x;     // over BATCH*512
    unsigned b = idx >> 9;
    unsigned i = (idx & 511u) << 1;
    float2 xv = *reinterpret_cast<const float2*>(x + ((size_t)b << 10) + i);
    float h0[9], h1[9];
    hermite_eval(xv.x, h0);
    hermite_eval(xv.y, h1);
    size_t base = (size_t)b * KTOT + i;
#pragma unroll
    for (int d = 0; d < 9; d++) {
        __half2 v = __floats2half2_rn(h0[d] * A_SCALE, h1[d] * A_SCALE);
        *reinterpret_cast<__half2*>(A + base + (size_t)d * IDIM) = v;
    }
}

// ---------------- kernel 2: coeff transpose -> fp16 B [ODIM, KTOT] ---------
__global__ void __launch_bounds__(256) coeff_transpose_kernel(const float* __restrict__ c,
                                                              __half* __restrict__ Bm) {
    __shared__ float tile[32][289];
    const int o0 = blockIdx.x * 32;
    const int i0 = blockIdx.y * 32;
    const int t = threadIdx.x;
#pragma unroll
    for (int p = 0; p < 36; p++) {                       // 32*288/256
        int idx = t + p * 256;
        int ii = idx / 288, j = idx % 288;
        tile[ii][j] = c[(size_t)(i0 + ii) * (ODIM * NDEG) + (size_t)o0 * NDEG + j];
    }
    __syncthreads();
#pragma unroll
    for (int p = 0; p < 36; p++) {
        int idx = t + p * 256;
        int ii = idx & 31;
        int r = idx >> 5;
        int d = r % 9, oo = r / 9;
        float v = tile[ii][oo * 9 + d] * B_SCALE;
        Bm[(size_t)(o0 + oo) * KTOT + (size_t)d * IDIM + (i0 + ii)] = __float2half_rn(v);
    }
}

// ---------------- kernel 3: PERSISTENT k-unit-balanced mma.sync GEMM -------
// Work = 36864 k-units (512 mn-tiles x 72). Each CTA takes a CONTIGUOUS range
// of ceil(NU/grid) units, accumulates across its k-iters of each mn tile in
// registers, one RED epilogue per mn segment (1-2 adds per output address).
__global__ void __launch_bounds__(288, 1) kan_gemm_kernel(
    const __grid_constant__ CUtensorMap tmA,
    const __grid_constant__ CUtensorMap tmB,
    float* __restrict__ out) {
    extern __shared__ __align__(128) char smem[];
    const uint32_t sb = smem_u32(smem);
    const uint32_t tiles = (sb + 128 + 1023) & ~1023u;   // 1024-aligned tile region
    const int tid = threadIdx.x;
    const int wid = tid >> 5;
    const int lid = tid & 31;

    const int upc = (NU + (int)gridDim.x - 1) / (int)gridDim.x;
    const int u0 = blockIdx.x * upc;
    const int u1 = (u0 + upc < NU) ? (u0 + upc) : NU;

    if (tid == 0) {
#pragma unroll
        for (int s = 0; s < STAGES; s++) {
            MBAR_INIT(sb + s * 16, 1);       // full (tx-based)
            MBAR_INIT(sb + s * 16 + 8, 8);   // empty (8 consumer warps)
        }
        FENCE_PROXY_ASYNC();                 // init visible to TMA proxy
    }
    __syncthreads();

    if (wid == 8) {
        // ---------------- producer: continuous TMA stream over k-units -----
        if (elect_one()) {
            int ph = 1, st = 0;
            for (int u = u0; u < u1; u++) {
                const int mn = u / KPT;
                const int kc = u - mn * KPT;
                const int n0 = (mn & 7) * BN;
                const int m0 = (mn >> 3) * BM;
                MBAR_WAIT(sb + st * 16 + 8, (uint32_t)ph);
                MBAR_EXPECT_TX(sb + st * 16, (uint32_t)STAGE_BYTES);
                const int cx0 = kc * 128;                // element coord of chunk 0
                const uint32_t base = tiles + st * STAGE_BYTES;
                TMA_LOAD_2D(base,                &tmA, cx0,      m0, sb + st * 16);
                TMA_LOAD_2D(base + SUB_TILE,     &tmA, cx0 + 64, m0, sb + st * 16);
                TMA_LOAD_2D(base + 2 * SUB_TILE, &tmB, cx0,      n0, sb + st * 16);
                TMA_LOAD_2D(base + 3 * SUB_TILE, &tmB, cx0 + 64, n0, sb + st * 16);
                if (++st == STAGES) { st = 0; ph ^= 1; }
            }
        }
        return;
    }

    // ---------------- consumers: 8 warps, 2(m) x 4(n), 64x32 each ----------
    const int wm = wid & 1;          // 0..1
    const int wn = wid >> 1;         // 0..3
    const int g  = lid >> 3;         // ldmatrix quad group 0..3
    const int lr = lid & 7;

    const int rA = wm * 64 + (g & 1) * 8 + lr;
    const uint32_t aRowOff = (uint32_t)rA * 128;
    const uint32_t maskA = (uint32_t)(rA & 7) * 16;
    const uint32_t cA0 = (uint32_t)(g >> 1) * 16;
    const int rB = wn * 32 + (g >> 1) * 8 + lr;
    const uint32_t bRowOff = (uint32_t)rB * 128;
    const uint32_t maskB = (uint32_t)(rB & 7) * 16;
    const uint32_t cB0 = (uint32_t)(g & 1) * 16;

    int ph = 0, st = 0;
    int u = u0;
    while (u < u1) {
        const int mn = u / KPT;
        const int useg = ((mn + 1) * KPT < u1) ? ((mn + 1) * KPT) : u1;  // segment end
        const int n0 = (mn & 7) * BN;
        const int m0 = (mn >> 3) * BM;

        float acc[4][4][4];
#pragma unroll
        for (int a = 0; a < 4; a++)
#pragma unroll
            for (int b = 0; b < 4; b++)
#pragma unroll
                for (int cc = 0; cc < 4; cc++) acc[a][b][cc] = 0.0f;

        for (; u < useg; u++) {
            MBAR_WAIT(sb + st * 16, (uint32_t)ph);
            const uint32_t base = tiles + st * STAGE_BYTES;
#pragma unroll
            for (int kk = 0; kk < 8; kk++) {             // 8 x K=16 per 128-wide stage
                const uint32_t aT = base + (uint32_t)(kk >> 2) * SUB_TILE;
                const uint32_t bT = base + 2 * SUB_TILE + (uint32_t)(kk >> 2) * SUB_TILE;
                const int kkl = kk & 3;
                const uint32_t cA = (cA0 + kkl * 32) ^ maskA;
                const uint32_t cB = (cB0 + kkl * 32) ^ maskB;
                uint32_t bf[2][4];
#pragma unroll
                for (int nt = 0; nt < 2; nt++) {
                    uint32_t addr = bT + bRowOff + (uint32_t)nt * (16 * 128) + cB;
                    LDSM_X4(bf[nt][0], bf[nt][1], bf[nt][2], bf[nt][3], addr);
                }
#pragma unroll
                for (int mt = 0; mt < 4; mt++) {
                    uint32_t a0, a1, a2, a3;
                    uint32_t addr = aT + aRowOff + (uint32_t)mt * (16 * 128) + cA;
                    LDSM_X4(a0, a1, a2, a3, addr);
                    MMA_16816(acc[mt][0], a0, a1, a2, a3, bf[0][0], bf[0][1]);
                    MMA_16816(acc[mt][1], a0, a1, a2, a3, bf[0][2], bf[0][3]);
                    MMA_16816(acc[mt][2], a0, a1, a2, a3, bf[1][0], bf[1][1]);
                    MMA_16816(acc[mt][3], a0, a1, a2, a3, bf[1][2], bf[1][3]);
                }
            }
            __syncwarp();                    // all lanes' smem reads done before release
            if (lid == 0) MBAR_ARRIVE(sb + st * 16 + 8);
            if (++st == STAGES) { st = 0; ph ^= 1; }
        }

        // epilogue for this mn segment: scaled RED-add into out
        const int mrow = m0 + wm * 64 + (lid >> 2);
        const int ncol = n0 + wn * 32 + 2 * (lid & 3);
#pragma unroll
        for (int mt = 0; mt < 4; mt++) {
#pragma unroll
            for (int j = 0; j < 4; j++) {
                float* p0 = out + (size_t)(mrow + mt * 16) * ODIM + (ncol + j * 8);
                float* p1 = p0 + 8 * ODIM;
                RED_ADD_V2F32(p0, acc[mt][j][0] * OUT_SCALE, acc[mt][j][1] * OUT_SCALE);
                RED_ADD_V2F32(p1, acc[mt][j][2] * OUT_SCALE, acc[mt][j][3] * OUT_SCALE);
            }
        }
    }
}

// ---------------- host launch ----------------
typedef CUresult (*PFN_encodeTiled_local)(
    CUtensorMap*, CUtensorMapDataType, cuuint32_t, void*,
    const cuuint64_t*, const cuuint64_t*, const cuuint32_t*, const cuuint32_t*,
    CUtensorMapInterleave, CUtensorMapSwizzle, CUtensorMapL2promotion,
    CUtensorMapFloatOOBfill);

extern "C" void kernel_launch(void* const* d_in, const int* in_sizes, int n_in,
                              void* d_out, int out_size) {
    const float* x = (const float*)d_in[0];
    const float* coeffs = (const float*)d_in[1];
    float* out = (float*)d_out;

    void* pA = nullptr;
    void* pB = nullptr;
    cudaGetSymbolAddress(&pA, g_A);
    cudaGetSymbolAddress(&pB, g_B);

    PFN_encodeTiled_local encode = nullptr;
    cudaDriverEntryPointQueryResult qr;
    cudaGetDriverEntryPoint("cuTensorMapEncodeTiled", (void**)&encode,
                            cudaEnableDefault, &qr);

    CUtensorMap tmA, tmB;
    {
        cuuint64_t dims[2] = {(cuuint64_t)KTOT, (cuuint64_t)BATCH};
        cuuint64_t strides[1] = {(cuuint64_t)KTOT * 2};
        cuuint32_t box[2] = {64u, (cuuint32_t)BM};
        cuuint32_t es[2] = {1, 1};
        encode(&tmA, CU_TENSOR_MAP_DATA_TYPE_FLOAT16, 2, pA, dims, strides, box, es,
               CU_TENSOR_MAP_INTERLEAVE_NONE, CU_TENSOR_MAP_SWIZZLE_128B,
               CU_TENSOR_MAP_L2_PROMOTION_L2_128B, CU_TENSOR_MAP_FLOAT_OOB_FILL_NONE);
    }
    {
        cuuint64_t dims[2] = {(cuuint64_t)KTOT, (cuuint64_t)ODIM};
        cuuint64_t strides[1] = {(cuuint64_t)KTOT * 2};
        cuuint32_t box[2] = {64u, (cuuint32_t)BN};
        cuuint32_t es[2] = {1, 1};
        encode(&tmB, CU_TENSOR_MAP_DATA_TYPE_FLOAT16, 2, pB, dims, strides, box, es,
               CU_TENSOR_MAP_INTERLEAVE_NONE, CU_TENSOR_MAP_SWIZZLE_128B,
               CU_TENSOR_MAP_L2_PROMOTION_L2_128B, CU_TENSOR_MAP_FLOAT_OOB_FILL_NONE);
    }

    cudaFuncSetAttribute(kan_gemm_kernel, cudaFuncAttributeMaxDynamicSharedMemorySize,
                         SMEM_BYTES);

    int dev = 0, nsm = 148;
    cudaGetDevice(&dev);
    cudaDeviceGetAttribute(&nsm, cudaDevAttrMultiProcessorCount, dev);
    if (nsm <= 0) nsm = 148;
    if (nsm > MNTILES) nsm = MNTILES;

    zero_kernel<<<(BATCH * ODIM / 4) / 256, 256>>>(out);
    hermite_basis_kernel<<<(BATCH * (IDIM / 2)) / 256, 256>>>(x, (__half*)pA);
    coeff_transpose_kernel<<<dim3(ODIM / 32, IDIM / 32), 256>>>(coeffs, (__half*)pB);
    kan_gemm_kernel<<<nsm, 288, SMEM_BYTES>>>(tmA, tmB, out);
}

// round 15
// speedup vs baseline: 1.5049x; 1.5049x over previous
#include <cuda_runtime.h>
#include <cuda.h>
#include <cuda_fp16.h>
#include <cstdint>

// ---------------- problem constants ----------------
static constexpr int BATCH = 8192;
static constexpr int IDIM  = 1024;
static constexpr int ODIM  = 1024;
static constexpr int NDEG  = 9;                 // DEGREE+1
static constexpr int KTOT  = NDEG * IDIM;       // 9216, k = d*1024 + i

static constexpr float A_SCALE   = 16.0f;
static constexpr float B_SCALE   = 4096.0f;
static constexpr float OUT_SCALE = 1.0f / (16.0f * 4096.0f);

// ---------------- GEMM config (persistent, hybrid fat/thin tail) -----------
static constexpr int BM = 128, BN = 128;
static constexpr int KSPLIT = 2;
static constexpr int KITERS = KTOT / 128 / KSPLIT;   // 36 per fat tile
static constexpr int THIN_ITERS = KITERS / 4;        // 9 per thin quarter
static constexpr int NTILES = (ODIM / BN) * (BATCH / BM) * KSPLIT;  // 1024 fat
static constexpr int STAGES = 3;
static constexpr int SUB_TILE   = BM * 128;          // 16384 bytes (one 64-chunk)
static constexpr int STAGE_BYTES = 4 * SUB_TILE;     // A0 A1 B0 B1 = 65536
static constexpr int SMEM_BYTES  = 2048 + STAGES * STAGE_BYTES; // 198656

// ---------------- scratch (static device globals; no cudaMalloc allowed) ----
__device__ __half g_A[(size_t)BATCH * KTOT];   // ~151 MB
__device__ __half g_B[(size_t)ODIM  * KTOT];   // ~19 MB

// ---------------- PTX helpers ----------------
__device__ __forceinline__ uint32_t smem_u32(const void* p) {
    uint32_t a;
    asm("{ .reg .u64 t; cvta.to.shared.u64 t, %1; cvt.u32.u64 %0, t; }" : "=r"(a) : "l"(p));
    return a;
}
__device__ __forceinline__ uint32_t elect_one() {
    uint32_t pred;
    asm volatile("{\n\t.reg .pred p;\n\telect.sync _|p, 0xFFFFFFFF;\n\tselp.b32 %0, 1, 0, p;\n\t}"
                 : "=r"(pred));
    return pred;
}

#define MBAR_INIT(addr, cnt) \
    asm volatile("mbarrier.init.shared.b64 [%0], %1;" :: "r"(addr), "r"(cnt) : "memory")
#define FENCE_PROXY_ASYNC() \
    asm volatile("fence.proxy.async.shared::cta;" ::: "memory")
#define MBAR_EXPECT_TX(addr, bytes) \
    asm volatile("mbarrier.arrive.expect_tx.shared.b64 _, [%0], %1;" :: "r"(addr), "r"(bytes) : "memory")
#define MBAR_ARRIVE(addr) \
    asm volatile("mbarrier.arrive.shared.b64 _, [%0];" :: "r"(addr) : "memory")

#define MBAR_WAIT(addr, parity) do {                                              \
    uint32_t _m = (addr); uint32_t _p = (parity); uint32_t _done;                 \
    asm volatile("{\n\t.reg .pred p;\n\t"                                         \
        "mbarrier.try_wait.parity.acquire.cta.shared::cta.b64 p, [%1], %2;\n\t"   \
        "selp.b32 %0, 1, 0, p;\n\t}"                                              \
        : "=r"(_done) : "r"(_m), "r"(_p) : "memory");                             \
    if (!_done) {                                                                 \
        asm volatile("{\n\t.reg .pred P1;\n\t"                                    \
            "WAIT_LOOP_%=:\n\t"                                                   \
            "mbarrier.try_wait.parity.acquire.cta.shared::cta.b64 P1, [%0], %1, 0x989680;\n\t" \
            "@P1 bra.uni WAIT_DONE_%=;\n\t"                                       \
            "bra.uni WAIT_LOOP_%=;\n\t"                                           \
            "WAIT_DONE_%=:\n\t}"                                                  \
            :: "r"(_m), "r"(_p) : "memory");                                      \
    }                                                                             \
} while (0)

#define TMA_LOAD_2D(smem_addr, tmap_ptr, cx, cy, mbar)                                     \
    asm volatile("cp.async.bulk.tensor.2d.shared::cta.global.tile.mbarrier::complete_tx::bytes " \
                 "[%0], [%1, {%2, %3}], [%4];"                                             \
                 :: "r"(smem_addr), "l"(tmap_ptr), "r"(cx), "r"(cy), "r"(mbar) : "memory")

#define LDSM_X4(r0, r1, r2, r3, addr)                                          \
    asm volatile("ldmatrix.sync.aligned.m8n8.x4.shared.b16 {%0,%1,%2,%3}, [%4];" \
                 : "=r"(r0), "=r"(r1), "=r"(r2), "=r"(r3) : "r"(addr))

#define MMA_16816(c, a0, a1, a2, a3, b0, b1)                                   \
    asm volatile("mma.sync.aligned.m16n8k16.row.col.f32.f16.f16.f32 "          \
                 "{%0,%1,%2,%3}, {%4,%5,%6,%7}, {%8,%9}, {%0,%1,%2,%3};"       \
                 : "+f"((c)[0]), "+f"((c)[1]), "+f"((c)[2]), "+f"((c)[3])      \
                 : "r"(a0), "r"(a1), "r"(a2), "r"(a3), "r"(b0), "r"(b1))

#define RED_ADD_V2F32(addr, vx, vy)                                            \
    asm volatile("red.global.add.v2.f32 [%0], {%1, %2};"                       \
                 :: "l"(addr), "f"(vx), "f"(vy) : "memory")

// ---------------- kernel 0: zero output ------------------------------------
__global__ void __launch_bounds__(256) zero_kernel(float* __restrict__ out) {
    size_t idx = ((size_t)blockIdx.x * 256 + threadIdx.x) * 4;
    *reinterpret_cast<float4*>(out + idx) = make_float4(0.f, 0.f, 0.f, 0.f);
}

// ---------------- kernel 1: Hermite basis -> fp16 A [BATCH, KTOT] ----------
__device__ __forceinline__ void hermite_eval(float xin, float* h) {
    const float e2x = __expf(2.0f * xin);
    const float th = 1.0f - __fdividef(2.0f, e2x + 1.0f);   // tanh(xin)
    const float t = th * 5.123105625617661f;                 // sqrt(17)+1
    const float g = __expf(-0.5f * t * t);
    h[0] = 0.7511255444649425f * g;                    // pi^-1/4 * gauss
    h[1] = 1.0622519320271968f * t * g;                // sqrt2 * pi^-1/4 * t * gauss
    const float ca[9] = {0.f, 0.f, 1.0f, 0.816496580927726f, 0.7071067811865476f,
                         0.6324555320336759f, 0.5773502691896258f,
                         0.5345224838248488f, 0.5f};
    const float cb[9] = {0.f, 0.f, 0.7071067811865476f, 0.816496580927726f,
                         0.8660254037844386f, 0.8944271909999159f,
                         0.9128709291752769f, 0.9258200997725514f, 0.9354143466934853f};
#pragma unroll
    for (int d = 2; d < 9; d++) h[d] = ca[d] * t * h[d - 1] - cb[d] * h[d - 2];
}

__global__ void __launch_bounds__(256) hermite_basis_kernel(const float* __restrict__ x,
                                                            __half* __restrict__ A) {
    unsigned idx = blockIdx.x * 256u + threadIdx.x;     // over BATCH*512
    unsigned b = idx >> 9;
    unsigned i = (idx & 511u) << 1;
    float2 xv = *reinterpret_cast<const float2*>(x + ((size_t)b << 10) + i);
    float h0[9], h1[9];
    hermite_eval(xv.x, h0);
    hermite_eval(xv.y, h1);
    size_t base = (size_t)b * KTOT + i;
#pragma unroll
    for (int d = 0; d < 9; d++) {
        __half2 v = __floats2half2_rn(h0[d] * A_SCALE, h1[d] * A_SCALE);
        *reinterpret_cast<__half2*>(A + base + (size_t)d * IDIM) = v;
    }
}

// ---------------- kernel 2: coeff transpose -> fp16 B [ODIM, KTOT] ---------
__global__ void __launch_bounds__(256) coeff_transpose_kernel(const float* __restrict__ c,
                                                              __half* __restrict__ Bm) {
    __shared__ float tile[32][289];
    const int o0 = blockIdx.x * 32;
    const int i0 = blockIdx.y * 32;
    const int t = threadIdx.x;
#pragma unroll
    for (int p = 0; p < 36; p++) {                       // 32*288/256
        int idx = t + p * 256;
        int ii = idx / 288, j = idx % 288;
        tile[ii][j] = c[(size_t)(i0 + ii) * (ODIM * NDEG) + (size_t)o0 * NDEG + j];
    }
    __syncthreads();
#pragma unroll
    for (int p = 0; p < 36; p++) {
        int idx = t + p * 256;
        int ii = idx & 31;
        int r = idx >> 5;
        int d = r % 9, oo = r / 9;
        float v = tile[ii][oo * 9 + d] * B_SCALE;
        Bm[(size_t)(o0 + oo) * KTOT + (size_t)d * IDIM + (i0 + ii)] = __float2half_rn(v);
    }
}

// ---------------- kernel 3: PERSISTENT hybrid fat/thin mma.sync GEMM -------
// Phase 1 (fat): FR = NTILES/grid full strided rounds (t = cta + r*grid) —
//   EXACT R12 access pattern (wave-synchronized k, full n coverage, L2 reuse).
// Phase 2 (thin): remaining tiles split into quarter-tiles (9 k-iters),
//   distributed ~evenly. Flattens makespan 252 -> 243 k-iters @152 SMs.
// RED-adds into pre-zeroed out; static schedule, commutative adds.
__global__ void __launch_bounds__(288, 1) kan_gemm_kernel(
    const __grid_constant__ CUtensorMap tmA,
    const __grid_constant__ CUtensorMap tmB,
    float* __restrict__ out) {
    extern __shared__ __align__(128) char smem[];
    const uint32_t sb = smem_u32(smem);
    const uint32_t tiles = (sb + 128 + 1023) & ~1023u;   // 1024-aligned tile region
    const int tid = threadIdx.x;
    const int wid = tid >> 5;
    const int lid = tid & 31;
    const int nsm = (int)gridDim.x;

    const int FR = NTILES / nsm;                 // fat rounds (6 @152)
    const int fatCount = FR * nsm;               // 912 @152
    const int thinTotal = (NTILES - fatCount) * 4;  // 448 @152
    const int tq = thinTotal / nsm, trem = thinTotal % nsm;
    const int j0 = (int)blockIdx.x * tq + ((int)blockIdx.x < trem ? (int)blockIdx.x : trem);
    const int j1 = j0 + tq + ((int)blockIdx.x < trem ? 1 : 0);

    if (tid == 0) {
#pragma unroll
        for (int s = 0; s < STAGES; s++) {
            MBAR_INIT(sb + s * 16, 1);       // full (tx-based)
            MBAR_INIT(sb + s * 16 + 8, 8);   // empty (8 consumer warps)
        }
        FENCE_PROXY_ASYNC();                 // init visible to TMA proxy
    }
    __syncthreads();

    if (wid == 8) {
        // ---------------- producer: continuous TMA stream ----------------
        if (elect_one()) {
            int ph = 1, st = 0;
            // fat phase: strided rounds (R12 pattern)
            for (int r = 0; r < FR; r++) {
                const int t = (int)blockIdx.x + r * nsm;
                const int n0 = (t & 7) * BN;
                const int m0 = ((t >> 3) & 63) * BM;
                const int kchunk0 = (t >> 9) * (KITERS * 2);
                for (int k = 0; k < KITERS; k++) {
                    MBAR_WAIT(sb + st * 16 + 8, (uint32_t)ph);
                    MBAR_EXPECT_TX(sb + st * 16, (uint32_t)STAGE_BYTES);
                    const int cx0 = (kchunk0 + 2 * k) * 64;
                    const uint32_t base = tiles + st * STAGE_BYTES;
                    TMA_LOAD_2D(base,                &tmA, cx0,      m0, sb + st * 16);
                    TMA_LOAD_2D(base + SUB_TILE,     &tmA, cx0 + 64, m0, sb + st * 16);
                    TMA_LOAD_2D(base + 2 * SUB_TILE, &tmB, cx0,      n0, sb + st * 16);
                    TMA_LOAD_2D(base + 3 * SUB_TILE, &tmB, cx0 + 64, n0, sb + st * 16);
                    if (++st == STAGES) { st = 0; ph ^= 1; }
                }
            }
            // thin phase: quarter tiles
            for (int j = j0; j < j1; j++) {
                const int t = fatCount + (j >> 2);
                const int q = j & 3;
                const int n0 = (t & 7) * BN;
                const int m0 = ((t >> 3) & 63) * BM;
                const int kchunk0 = (t >> 9) * (KITERS * 2) + q * (THIN_ITERS * 2);
                for (int k = 0; k < THIN_ITERS; k++) {
                    MBAR_WAIT(sb + st * 16 + 8, (uint32_t)ph);
                    MBAR_EXPECT_TX(sb + st * 16, (uint32_t)STAGE_BYTES);
                    const int cx0 = (kchunk0 + 2 * k) * 64;
                    const uint32_t base = tiles + st * STAGE_BYTES;
                    TMA_LOAD_2D(base,                &tmA, cx0,      m0, sb + st * 16);
                    TMA_LOAD_2D(base + SUB_TILE,     &tmA, cx0 + 64, m0, sb + st * 16);
                    TMA_LOAD_2D(base + 2 * SUB_TILE, &tmB, cx0,      n0, sb + st * 16);
                    TMA_LOAD_2D(base + 3 * SUB_TILE, &tmB, cx0 + 64, n0, sb + st * 16);
                    if (++st == STAGES) { st = 0; ph ^= 1; }
                }
            }
        }
        return;
    }

    // ---------------- consumers: 8 warps, 2(m) x 4(n), 64x32 each ----------
    const int wm = wid & 1;          // 0..1
    const int wn = wid >> 1;         // 0..3
    const int g  = lid >> 3;         // ldmatrix quad group 0..3
    const int lr = lid & 7;

    const int rA = wm * 64 + (g & 1) * 8 + lr;
    const uint32_t aRowOff = (uint32_t)rA * 128;
    const uint32_t maskA = (uint32_t)(rA & 7) * 16;
    const uint32_t cA0 = (uint32_t)(g >> 1) * 16;
    const int rB = wn * 32 + (g >> 1) * 8 + lr;
    const uint32_t bRowOff = (uint32_t)rB * 128;
    const uint32_t maskB = (uint32_t)(rB & 7) * 16;
    const uint32_t cB0 = (uint32_t)(g & 1) * 16;

    int ph = 0, st = 0;
    // two phases: p=0 fat (FR segments of KITERS), p=1 thin (j segs of THIN_ITERS)
    for (int phase = 0; phase < 2; phase++) {
        const int segs = (phase == 0) ? FR : (j1 - j0);
        const int iters = (phase == 0) ? KITERS : THIN_ITERS;
        for (int s = 0; s < segs; s++) {
            int t;
            if (phase == 0) t = (int)blockIdx.x + s * nsm;
            else            t = fatCount + ((j0 + s) >> 2);
            const int n0 = (t & 7) * BN;
            const int m0 = ((t >> 3) & 63) * BM;

            float acc[4][4][4];
#pragma unroll
            for (int a = 0; a < 4; a++)
#pragma unroll
                for (int b = 0; b < 4; b++)
#pragma unroll
                    for (int cc = 0; cc < 4; cc++) acc[a][b][cc] = 0.0f;

            for (int k = 0; k < iters; k++) {
                MBAR_WAIT(sb + st * 16, (uint32_t)ph);
                const uint32_t base = tiles + st * STAGE_BYTES;
#pragma unroll
                for (int kk = 0; kk < 8; kk++) {         // 8 x K=16 per 128-wide stage
                    const uint32_t aT = base + (uint32_t)(kk >> 2) * SUB_TILE;
                    const uint32_t bT = base + 2 * SUB_TILE + (uint32_t)(kk >> 2) * SUB_TILE;
                    const int kkl = kk & 3;
                    const uint32_t cA = (cA0 + kkl * 32) ^ maskA;
                    const uint32_t cB = (cB0 + kkl * 32) ^ maskB;
                    uint32_t bf[2][4];
#pragma unroll
                    for (int nt = 0; nt < 2; nt++) {
                        uint32_t addr = bT + bRowOff + (uint32_t)nt * (16 * 128) + cB;
                        LDSM_X4(bf[nt][0], bf[nt][1], bf[nt][2], bf[nt][3], addr);
                    }
#pragma unroll
                    for (int mt = 0; mt < 4; mt++) {
                        uint32_t a0, a1, a2, a3;
                        uint32_t addr = aT + aRowOff + (uint32_t)mt * (16 * 128) + cA;
                        LDSM_X4(a0, a1, a2, a3, addr);
                        MMA_16816(acc[mt][0], a0, a1, a2, a3, bf[0][0], bf[0][1]);
                        MMA_16816(acc[mt][1], a0, a1, a2, a3, bf[0][2], bf[0][3]);
                        MMA_16816(acc[mt][2], a0, a1, a2, a3, bf[1][0], bf[1][1]);
                        MMA_16816(acc[mt][3], a0, a1, a2, a3, bf[1][2], bf[1][3]);
                    }
                }
                __syncwarp();                // all lanes' smem reads done before release
                if (lid == 0) MBAR_ARRIVE(sb + st * 16 + 8);
                if (++st == STAGES) { st = 0; ph ^= 1; }
            }

            // epilogue: scaled RED-add into out
            const int mrow = m0 + wm * 64 + (lid >> 2);
            const int ncol = n0 + wn * 32 + 2 * (lid & 3);
#pragma unroll
            for (int mt = 0; mt < 4; mt++) {
#pragma unroll
                for (int j = 0; j < 4; j++) {
                    float* p0 = out + (size_t)(mrow + mt * 16) * ODIM + (ncol + j * 8);
                    float* p1 = p0 + 8 * ODIM;
                    RED_ADD_V2F32(p0, acc[mt][j][0] * OUT_SCALE, acc[mt][j][1] * OUT_SCALE);
                    RED_ADD_V2F32(p1, acc[mt][j][2] * OUT_SCALE, acc[mt][j][3] * OUT_SCALE);
                }
            }
        }
    }
}

// ---------------- host launch ----------------
typedef CUresult (*PFN_encodeTiled_local)(
    CUtensorMap*, CUtensorMapDataType, cuuint32_t, void*,
    const cuuint64_t*, const cuuint64_t*, const cuuint32_t*, const cuuint32_t*,
    CUtensorMapInterleave, CUtensorMapSwizzle, CUtensorMapL2promotion,
    CUtensorMapFloatOOBfill);

extern "C" void kernel_launch(void* const* d_in, const int* in_sizes, int n_in,
                              void* d_out, int out_size) {
    const float* x = (const float*)d_in[0];
    const float* coeffs = (const float*)d_in[1];
    float* out = (float*)d_out;

    void* pA = nullptr;
    void* pB = nullptr;
    cudaGetSymbolAddress(&pA, g_A);
    cudaGetSymbolAddress(&pB, g_B);

    PFN_encodeTiled_local encode = nullptr;
    cudaDriverEntryPointQueryResult qr;
    cudaGetDriverEntryPoint("cuTensorMapEncodeTiled", (void**)&encode,
                            cudaEnableDefault, &qr);

    CUtensorMap tmA, tmB;
    {
        cuuint64_t dims[2] = {(cuuint64_t)KTOT, (cuuint64_t)BATCH};
        cuuint64_t strides[1] = {(cuuint64_t)KTOT * 2};
        cuuint32_t box[2] = {64u, (cuuint32_t)BM};
        cuuint32_t es[2] = {1, 1};
        encode(&tmA, CU_TENSOR_MAP_DATA_TYPE_FLOAT16, 2, pA, dims, strides, box, es,
               CU_TENSOR_MAP_INTERLEAVE_NONE, CU_TENSOR_MAP_SWIZZLE_128B,
               CU_TENSOR_MAP_L2_PROMOTION_L2_128B, CU_TENSOR_MAP_FLOAT_OOB_FILL_NONE);
    }
    {
        cuuint64_t dims[2] = {(cuuint64_t)KTOT, (cuuint64_t)ODIM};
        cuuint64_t strides[1] = {(cuuint64_t)KTOT * 2};
        cuuint32_t box[2] = {64u, (cuuint32_t)BN};
        cuuint32_t es[2] = {1, 1};
        encode(&tmB, CU_TENSOR_MAP_DATA_TYPE_FLOAT16, 2, pB, dims, strides, box, es,
               CU_TENSOR_MAP_INTERLEAVE_NONE, CU_TENSOR_MAP_SWIZZLE_128B,
               CU_TENSOR_MAP_L2_PROMOTION_L2_128B, CU_TENSOR_MAP_FLOAT_OOB_FILL_NONE);
    }

    cudaFuncSetAttribute(kan_gemm_kernel, cudaFuncAttributeMaxDynamicSharedMemorySize,
                         SMEM_BYTES);

    int dev = 0, nsm = 148;
    cudaGetDevice(&dev);
    cudaDeviceGetAttribute(&nsm, cudaDevAttrMultiProcessorCount, dev);
    if (nsm <= 0) nsm = 148;
    if (nsm > NTILES) nsm = NTILES;

    zero_kernel<<<(BATCH * ODIM / 4) / 256, 256>>>(out);
    hermite_basis_kernel<<<(BATCH * (IDIM / 2)) / 256, 256>>>(x, (__half*)pA);
    coeff_transpose_kernel<<<dim3(ODIM / 32, IDIM / 32), 256>>>(coeffs, (__half*)pB);
    kan_gemm_kernel<<<nsm, 288, SMEM_BYTES>>>(tmA, tmB, out);
}